// round 7
// baseline (speedup 1.0000x reference)
#include <cuda_runtime.h>
#include <cuda_fp16.h>
#include <stdint.h>

#define L_SEQ   2048
#define BATCH   16
#define N_IN    1024
#define N_OUT   1024
#define M_ROWS  (L_SEQ * BATCH)      // 32768
#define N_COLS  (2 * N_OUT)          // 2048
#define K_DIM   1024
#define NCH     (BATCH * N_OUT)      // 16384 chains

#define CS_OFF      0
#define CFINAL_OFF  (M_ROWS * N_OUT)
#define FORGET_OFF  (M_ROWS * N_OUT + BATCH * N_OUT)

// fp16 operands. A: [32768,1024] k-contig. B = fp16(W^T): [2048,1024].
__device__ __half g_Ah[(size_t)M_ROWS * K_DIM];
__device__ __half g_Bh[(size_t)N_COLS * K_DIM];

// scan scratch. One segment = one GEMM M-tile = 16 l-steps.
#define SEGS 128
#define SEG_LEN (L_SEQ / SEGS)       // 16
__device__ float g_F  [SEGS][NCH];
__device__ float g_U  [SEGS][NCH];
__device__ float g_Cin[SEGS][NCH];

// ---------------------------------------------------------------------------
__device__ __forceinline__ uint32_t s2u(const void* p) {
    uint32_t r;
    asm("{ .reg .u64 t; cvta.to.shared.u64 t, %1; cvt.u32.u64 %0, t; }"
        : "=r"(r) : "l"(p));
    return r;
}
__device__ __forceinline__ void cp16(uint32_t saddr, const void* gptr) {
    uint64_t g = (uint64_t)__cvta_generic_to_global(gptr);
    asm volatile("cp.async.cg.shared.global [%0], [%1], 16;"
                 :: "r"(saddr), "l"(g) : "memory");
}
__device__ __forceinline__ void cp_commit() {
    asm volatile("cp.async.commit_group;" ::: "memory");
}
template <int N>
__device__ __forceinline__ void cp_wait() {
    asm volatile("cp.async.wait_group %0;" :: "n"(N) : "memory");
}
__device__ __forceinline__ void ldsm4(uint32_t* r, uint32_t addr) {
    asm volatile("ldmatrix.sync.aligned.m8n8.x4.shared.b16 {%0,%1,%2,%3}, [%4];"
                 : "=r"(r[0]), "=r"(r[1]), "=r"(r[2]), "=r"(r[3]) : "r"(addr));
}
__device__ __forceinline__ void mma16816(float* d, const uint32_t* a, const uint32_t* b) {
    asm volatile(
        "mma.sync.aligned.m16n8k16.row.col.f32.f16.f16.f32 "
        "{%0,%1,%2,%3}, {%4,%5,%6,%7}, {%8,%9}, {%0,%1,%2,%3};"
        : "+f"(d[0]), "+f"(d[1]), "+f"(d[2]), "+f"(d[3])
        : "r"(a[0]), "r"(a[1]), "r"(a[2]), "r"(a[3]), "r"(b[0]), "r"(b[1]));
}
__device__ __forceinline__ uint32_t swz(uint32_t off) {
    return off ^ ((off >> 3) & 0x70);
}

// ---------------------------------------------------------------------------
// Operand prep
// ---------------------------------------------------------------------------
__global__ __launch_bounds__(256)
void convert_a_kernel(const float* __restrict__ A) {
    size_t i = ((size_t)blockIdx.x * 256 + threadIdx.x) * 8;
    float4 v0 = *reinterpret_cast<const float4*>(A + i);
    float4 v1 = *reinterpret_cast<const float4*>(A + i + 4);
    __half2 h0 = __floats2half2_rn(v0.x, v0.y);
    __half2 h1 = __floats2half2_rn(v0.z, v0.w);
    __half2 h2 = __floats2half2_rn(v1.x, v1.y);
    __half2 h3 = __floats2half2_rn(v1.z, v1.w);
    uint4 pk;
    pk.x = *reinterpret_cast<uint32_t*>(&h0);
    pk.y = *reinterpret_cast<uint32_t*>(&h1);
    pk.z = *reinterpret_cast<uint32_t*>(&h2);
    pk.w = *reinterpret_cast<uint32_t*>(&h3);
    *reinterpret_cast<uint4*>(g_Ah + i) = pk;
}

__global__ __launch_bounds__(256)
void convert_b_kernel(const float* __restrict__ W) {
    __shared__ float t[32][33];
    int n0 = blockIdx.x * 32;
    int k0 = blockIdx.y * 32;
    int tx = threadIdx.x & 31;
    int ty = threadIdx.x >> 5;
#pragma unroll
    for (int i = 0; i < 4; i++)
        t[ty + i * 8][tx] = W[(size_t)(k0 + ty + i * 8) * N_COLS + n0 + tx];
    __syncthreads();
#pragma unroll
    for (int i = 0; i < 4; i++) {
        int n = ty + i * 8;
        g_Bh[(size_t)(n0 + n) * K_DIM + k0 + tx] = __float2half_rn(t[tx][n]);
    }
}

// ---------------------------------------------------------------------------
// GEMM: BM=256, BN=128, BK=64, 512 threads = 16 warps (4M x 4N),
// warp tile 64x32. C = Ah * Bh, fp32 accum. 3-stage cp.async pipeline.
// Epilogue: gates + per-segment scan summaries (fused phaseA).
// ---------------------------------------------------------------------------
#define BK 64
#define OFF_A 0
#define OFF_B 32768
#define STAGE_BYTES 49152
#define NSTAGE 3
#define SMEM_TOTAL (NSTAGE * STAGE_BYTES)   // 147456
#define NCHUNK (K_DIM / BK)                 // 16

__device__ __forceinline__ void load_stage(uint32_t sbase, int tid,
                                           int rowBase, int colBase, int k0) {
    const char* ah = reinterpret_cast<const char*>(g_Ah);
    const char* bh = reinterpret_cast<const char*>(g_Bh);
#pragma unroll
    for (int i = 0; i < 4; i++) {               // A: 256 rows x 8 x 16B
        int idx = i * 512 + tid;
        int row = idx >> 3, c = idx & 7;
        uint32_t so = swz((uint32_t)(row * 128 + c * 16));
        size_t go = ((size_t)(rowBase + row) * K_DIM + k0) * 2 + c * 16;
        cp16(sbase + OFF_A + so, ah + go);
    }
#pragma unroll
    for (int i = 0; i < 2; i++) {               // B: 128 rows x 8 x 16B
        int idx = i * 512 + tid;
        int row = idx >> 3, c = idx & 7;
        uint32_t so = swz((uint32_t)(row * 128 + c * 16));
        size_t go = ((size_t)(colBase + row) * K_DIM + k0) * 2 + c * 16;
        cp16(sbase + OFF_B + so, bh + go);
    }
    cp_commit();
}

__global__ __launch_bounds__(512, 1)
void gemm_mma_kernel(const float* __restrict__ bias,
                     float* __restrict__ u0_out,
                     float* __restrict__ f_out) {
    extern __shared__ char smem[];
    const uint32_t sb = s2u(smem);
    const int tid = threadIdx.x;
    const int lid = tid & 31;
    const int wid = tid >> 5;            // 0..15
    const int warpM = wid & 3;           // 4 x 64-row slices
    const int warpN = wid >> 2;          // 4 x 32-col slices
    const int colBase = blockIdx.x * 128;
    const int rowBase = blockIdx.y * 256;

    float acc[4][4][4];
#pragma unroll
    for (int mi = 0; mi < 4; mi++)
#pragma unroll
        for (int ni = 0; ni < 4; ni++)
#pragma unroll
            for (int e = 0; e < 4; e++)
                acc[mi][ni][e] = 0.0f;

    // prologue: fill all 3 stages
#pragma unroll
    for (int s = 0; s < NSTAGE; s++)
        load_stage(sb + s * STAGE_BYTES, tid, rowBase, colBase, s * BK);

    const int aRowIn = warpM * 64 + (lid & 15);
    const int aKIn   = (lid >> 4) * 8;
    const int bRowIn = warpN * 32 + (lid & 7) + ((lid >> 4) & 1) * 8;
    const int bKIn   = ((lid >> 3) & 1) * 8;

    int bufc = 0;
    for (int c = 0; c < NCHUNK; c++) {
        // retire chunk c's cp.async group: pending must drop to
        // min(NSTAGE, NCHUNK - c) - 1
        if (c + 2 < NCHUNK)      cp_wait<2>();
        else if (c + 1 < NCHUNK) cp_wait<1>();
        else                     cp_wait<0>();
        __syncthreads();

        const uint32_t sbase = sb + bufc * STAGE_BYTES;
        const uint32_t aS = sbase + OFF_A;
        const uint32_t bS = sbase + OFF_B;

#pragma unroll
        for (int ks = 0; ks < 4; ks++) {
            const int kb = ks * 16;
            uint32_t ah[4][4];
#pragma unroll
            for (int mi = 0; mi < 4; mi++) {
                uint32_t off = swz((uint32_t)((aRowIn + mi * 16) * 128 +
                                              (kb + aKIn) * 2));
                ldsm4(ah[mi], aS + off);
            }
            uint32_t bh[4][2];
#pragma unroll
            for (int nt = 0; nt < 2; nt++) {
                uint32_t off = swz((uint32_t)((bRowIn + nt * 16) * 128 +
                                              (kb + bKIn) * 2));
                uint32_t r[4];
                ldsm4(r, bS + off);
                bh[nt * 2][0] = r[0]; bh[nt * 2][1] = r[1];
                bh[nt * 2 + 1][0] = r[2]; bh[nt * 2 + 1][1] = r[3];
            }
#pragma unroll
            for (int mi = 0; mi < 4; mi++)
#pragma unroll
                for (int ni = 0; ni < 4; ni++)
                    mma16816(acc[mi][ni], ah[mi], bh[ni]);
        }

        __syncthreads();
        if (c + NSTAGE < NCHUNK)
            load_stage(sbase, tid, rowBase, colBase, (c + NSTAGE) * BK);
        bufc = (bufc == NSTAGE - 1) ? 0 : bufc + 1;
    }
    __syncthreads();   // safe to reuse smem for scan partials

    // ------------- epilogue: gates + stores + fused segment summary -------------
    // Lane owns chains (b0, o) and (b1, o) per ni; b0 = lid>>2, b1 = b0+8.
    // l_local of acc[mi] = warpM*4 + mi (sequential in mi, across warpM in smem).
    float2* part = reinterpret_cast<float2*>(smem);   // [wM][wN][ni][half][lane]

    const int rBase = rowBase + warpM * 64 + (lid >> 2);
    const int oLane = (lid & 3);

#pragma unroll
    for (int ni = 0; ni < 4; ni++) {
        const int o = ((colBase + warpN * 32 + ni * 8) >> 1) + oLane;
        const float fb = __ldg(bias + N_OUT + o);
        float F0 = 1.0f, U0 = 0.0f, F1 = 1.0f, U1 = 0.0f;
#pragma unroll
        for (int mi = 0; mi < 4; mi++) {
            const int r0 = rBase + mi * 16;
            const int r1 = r0 + 8;
            float f0 = 1.0f / (1.0f + __expf(-(acc[mi][ni][1] + fb)));
            float u0 = acc[mi][ni][0] * (1.0f - f0);
            float f1 = 1.0f / (1.0f + __expf(-(acc[mi][ni][3] + fb)));
            float u1 = acc[mi][ni][2] * (1.0f - f1);
            u0_out[(size_t)r0 * N_OUT + o] = u0;
            f_out [(size_t)r0 * N_OUT + o] = f0;
            u0_out[(size_t)r1 * N_OUT + o] = u1;
            f_out [(size_t)r1 * N_OUT + o] = f1;
            U0 = fmaf(U0, f0, u0); F0 *= f0;
            U1 = fmaf(U1, f1, u1); F1 *= f1;
        }
        int base = ((warpM * 4 + warpN) * 4 + ni) * 64;
        part[base + lid]      = make_float2(F0, U0);
        part[base + 32 + lid] = make_float2(F1, U1);
    }
    __syncthreads();

    // combine partials across warpM (l-order) and write g_F/g_U
    const int seg = blockIdx.y;
#pragma unroll
    for (int it = 0; it < 2; it++) {
        int item = tid + it * 512;              // [wN(2b)|ni(2b)|half(1b)|lane(5b)]
        int iwN   = item >> 8;
        int ini   = (item >> 6) & 3;
        int ihalf = (item >> 5) & 1;
        int ilane = item & 31;
        float F = 1.0f, U = 0.0f;
#pragma unroll
        for (int w = 0; w < 4; w++) {
            float2 p = part[(((w * 4 + iwN) * 4 + ini) * 2 + ihalf) * 32 + ilane];
            U = fmaf(U, p.x, p.y);
            F *= p.x;
        }
        int b = (ilane >> 2) + ihalf * 8;
        int j = b * N_OUT + blockIdx.x * 64 + iwN * 16 + ini * 4 + (ilane & 3);
        g_F[seg][j] = F;
        g_U[seg][j] = U;
    }
}

// ---------------------------------------------------------------------------
// Scan phases B (global combine) and C (replay). 128 segments x 16 steps.
// ---------------------------------------------------------------------------
__global__ __launch_bounds__(256)
void scan_phaseB(const float* __restrict__ c_init,
                 float* __restrict__ c_final) {
    const int j = blockIdx.x * 256 + threadIdx.x;
    float c = c_init[j];
#pragma unroll 8
    for (int s = 0; s < SEGS; s++) {
        g_Cin[s][j] = c;
        c = fmaf(c, g_F[s][j], g_U[s][j]);
    }
    c_final[j] = c;
}

__global__ __launch_bounds__(256)
void scan_phaseC(float* __restrict__ cs,
                 const float* __restrict__ f) {
    const int j = blockIdx.x * 256 + threadIdx.x;
    const int s = blockIdx.y;
    size_t idx = (size_t)s * SEG_LEN * NCH + j;
    float c = g_Cin[s][j];
#pragma unroll
    for (int t = 0; t < SEG_LEN; t++) {
        float ft = f[idx];
        float ut = cs[idx];
        c = fmaf(c, ft, ut);
        cs[idx] = c;
        idx += NCH;
    }
}

// ---------------------------------------------------------------------------
extern "C" void kernel_launch(void* const* d_in, const int* in_sizes, int n_in,
                              void* d_out, int out_size)
{
    const float* input  = (const float*)d_in[0];
    const float* c_init = (const float*)d_in[1];
    const float* weight = (const float*)d_in[2];
    const float* bias   = (const float*)d_in[3];

    float* out    = (float*)d_out;
    float* cs     = out + CS_OFF;
    float* cfin   = out + CFINAL_OFF;
    float* forget = out + FORGET_OFF;

    cudaFuncSetAttribute(gemm_mma_kernel,
                         cudaFuncAttributeMaxDynamicSharedMemorySize, SMEM_TOTAL);

    convert_a_kernel<<<(M_ROWS * K_DIM) / (256 * 8), 256>>>(input);
    convert_b_kernel<<<dim3(N_COLS / 32, K_DIM / 32), 256>>>(weight);

    dim3 grid(N_COLS / 128, M_ROWS / 256);   // (16, 128) — blockIdx.y = segment
    gemm_mma_kernel<<<grid, 512, SMEM_TOTAL>>>(bias, cs, forget);

    scan_phaseB<<<NCH / 256, 256>>>(c_init, cfin);
    dim3 cgrid(NCH / 256, SEGS);
    scan_phaseC<<<cgrid, 256>>>(cs, forget);
}

// round 9
// speedup vs baseline: 1.0897x; 1.0897x over previous
#include <cuda_runtime.h>
#include <cuda_fp16.h>
#include <stdint.h>

#define L_SEQ   2048
#define BATCH   16
#define N_IN    1024
#define N_OUT   1024
#define M_ROWS  (L_SEQ * BATCH)      // 32768
#define N_COLS  (2 * N_OUT)          // 2048
#define K_DIM   1024
#define NCH     (BATCH * N_OUT)      // 16384 chains

#define CS_OFF      0
#define CFINAL_OFF  (M_ROWS * N_OUT)
#define FORGET_OFF  (M_ROWS * N_OUT + BATCH * N_OUT)

// fp16 operands. A: [32768,1024] k-contig. B = fp16(W^T): [2048,1024].
__device__ __half g_Ah[(size_t)M_ROWS * K_DIM];
__device__ __half g_Bh[(size_t)N_COLS * K_DIM];

// scan scratch. One segment = one GEMM M-tile = 16 l-steps.
#define SEGS 128
#define SEG_LEN (L_SEQ / SEGS)       // 16
__device__ float g_F  [SEGS][NCH];
__device__ float g_U  [SEGS][NCH];
__device__ float g_Cin[SEGS][NCH];

// ---------------------------------------------------------------------------
__device__ __forceinline__ uint32_t s2u(const void* p) {
    uint32_t r;
    asm("{ .reg .u64 t; cvta.to.shared.u64 t, %1; cvt.u32.u64 %0, t; }"
        : "=r"(r) : "l"(p));
    return r;
}
__device__ __forceinline__ void cp16(uint32_t saddr, const void* gptr) {
    uint64_t g = (uint64_t)__cvta_generic_to_global(gptr);
    asm volatile("cp.async.cg.shared.global [%0], [%1], 16;"
                 :: "r"(saddr), "l"(g) : "memory");
}
__device__ __forceinline__ void cp_commit() {
    asm volatile("cp.async.commit_group;" ::: "memory");
}
template <int N>
__device__ __forceinline__ void cp_wait() {
    asm volatile("cp.async.wait_group %0;" :: "n"(N) : "memory");
}
__device__ __forceinline__ void ldsm4(uint32_t* r, uint32_t addr) {
    asm volatile("ldmatrix.sync.aligned.m8n8.x4.shared.b16 {%0,%1,%2,%3}, [%4];"
                 : "=r"(r[0]), "=r"(r[1]), "=r"(r[2]), "=r"(r[3]) : "r"(addr));
}
__device__ __forceinline__ void mma16816(float* d, const uint32_t* a, const uint32_t* b) {
    asm volatile(
        "mma.sync.aligned.m16n8k16.row.col.f32.f16.f16.f32 "
        "{%0,%1,%2,%3}, {%4,%5,%6,%7}, {%8,%9}, {%0,%1,%2,%3};"
        : "+f"(d[0]), "+f"(d[1]), "+f"(d[2]), "+f"(d[3])
        : "r"(a[0]), "r"(a[1]), "r"(a[2]), "r"(a[3]), "r"(b[0]), "r"(b[1]));
}
__device__ __forceinline__ uint32_t swz(uint32_t off) {
    return off ^ ((off >> 3) & 0x70);
}

// ---------------------------------------------------------------------------
// Operand prep
// ---------------------------------------------------------------------------
__global__ __launch_bounds__(256)
void convert_a_kernel(const float* __restrict__ A) {
    size_t i = ((size_t)blockIdx.x * 256 + threadIdx.x) * 8;
    float4 v0 = *reinterpret_cast<const float4*>(A + i);
    float4 v1 = *reinterpret_cast<const float4*>(A + i + 4);
    __half2 h0 = __floats2half2_rn(v0.x, v0.y);
    __half2 h1 = __floats2half2_rn(v0.z, v0.w);
    __half2 h2 = __floats2half2_rn(v1.x, v1.y);
    __half2 h3 = __floats2half2_rn(v1.z, v1.w);
    uint4 pk;
    pk.x = *reinterpret_cast<uint32_t*>(&h0);
    pk.y = *reinterpret_cast<uint32_t*>(&h1);
    pk.z = *reinterpret_cast<uint32_t*>(&h2);
    pk.w = *reinterpret_cast<uint32_t*>(&h3);
    *reinterpret_cast<uint4*>(g_Ah + i) = pk;
}

__global__ __launch_bounds__(256)
void convert_b_kernel(const float* __restrict__ W) {
    __shared__ float t[32][33];
    int n0 = blockIdx.x * 32;
    int k0 = blockIdx.y * 32;
    int tx = threadIdx.x & 31;
    int ty = threadIdx.x >> 5;
#pragma unroll
    for (int i = 0; i < 4; i++)
        t[ty + i * 8][tx] = W[(size_t)(k0 + ty + i * 8) * N_COLS + n0 + tx];
    __syncthreads();
#pragma unroll
    for (int i = 0; i < 4; i++) {
        int n = ty + i * 8;
        g_Bh[(size_t)(n0 + n) * K_DIM + k0 + tx] = __float2half_rn(t[tx][n]);
    }
}

// ---------------------------------------------------------------------------
// GEMM: BM=256, BN=128, BK=64, 512 threads = 16 warps (4M x 4N),
// warp tile 64x32. C = Ah * Bh, fp32 accum. 3-stage cp.async pipeline.
// Epilogue: gates + per-segment scan summaries (fused phaseA).
// ---------------------------------------------------------------------------
#define BK 64
#define OFF_A 0
#define OFF_B 32768
#define STAGE_BYTES 49152
#define NSTAGE 3
#define SMEM_TOTAL (NSTAGE * STAGE_BYTES)   // 147456
#define NCHUNK (K_DIM / BK)                 // 16

__device__ __forceinline__ void load_stage(uint32_t sbase, int tid,
                                           int rowBase, int colBase, int k0) {
    const char* ah = reinterpret_cast<const char*>(g_Ah);
    const char* bh = reinterpret_cast<const char*>(g_Bh);
#pragma unroll
    for (int i = 0; i < 4; i++) {               // A: 256 rows x 8 x 16B
        int idx = i * 512 + tid;
        int row = idx >> 3, c = idx & 7;
        uint32_t so = swz((uint32_t)(row * 128 + c * 16));
        size_t go = ((size_t)(rowBase + row) * K_DIM + k0) * 2 + c * 16;
        cp16(sbase + OFF_A + so, ah + go);
    }
#pragma unroll
    for (int i = 0; i < 2; i++) {               // B: 128 rows x 8 x 16B
        int idx = i * 512 + tid;
        int row = idx >> 3, c = idx & 7;
        uint32_t so = swz((uint32_t)(row * 128 + c * 16));
        size_t go = ((size_t)(colBase + row) * K_DIM + k0) * 2 + c * 16;
        cp16(sbase + OFF_B + so, bh + go);
    }
    cp_commit();
}

__global__ __launch_bounds__(512, 1)
void gemm_mma_kernel(const float* __restrict__ bias,
                     float* __restrict__ u0_out,
                     float* __restrict__ f_out) {
    extern __shared__ char smem[];
    const uint32_t sb = s2u(smem);
    const int tid = threadIdx.x;
    const int lid = tid & 31;
    const int wid = tid >> 5;            // 0..15
    const int warpM = wid & 3;           // 4 x 64-row slices
    const int warpN = wid >> 2;          // 4 x 32-col slices
    const int colBase = blockIdx.x * 128;
    const int rowBase = blockIdx.y * 256;

    float acc[4][4][4];
#pragma unroll
    for (int mi = 0; mi < 4; mi++)
#pragma unroll
        for (int ni = 0; ni < 4; ni++)
#pragma unroll
            for (int e = 0; e < 4; e++)
                acc[mi][ni][e] = 0.0f;

    // prologue: fill all 3 stages
#pragma unroll
    for (int s = 0; s < NSTAGE; s++)
        load_stage(sb + s * STAGE_BYTES, tid, rowBase, colBase, s * BK);

    const int aRowIn = warpM * 64 + (lid & 15);
    const int aKIn   = (lid >> 4) * 8;
    const int bRowIn = warpN * 32 + (lid & 7) + ((lid >> 4) & 1) * 8;
    const int bKIn   = ((lid >> 3) & 1) * 8;

    int bufc = 0;
    for (int c = 0; c < NCHUNK; c++) {
        // retire chunk c's cp.async group: pending must drop to
        // min(NSTAGE, NCHUNK - c) - 1
        if (c + 2 < NCHUNK)      cp_wait<2>();
        else if (c + 1 < NCHUNK) cp_wait<1>();
        else                     cp_wait<0>();
        __syncthreads();

        const uint32_t sbase = sb + bufc * STAGE_BYTES;
        const uint32_t aS = sbase + OFF_A;
        const uint32_t bS = sbase + OFF_B;

#pragma unroll
        for (int ks = 0; ks < 4; ks++) {
            const int kb = ks * 16;
            uint32_t ah[4][4];
#pragma unroll
            for (int mi = 0; mi < 4; mi++) {
                uint32_t off = swz((uint32_t)((aRowIn + mi * 16) * 128 +
                                              (kb + aKIn) * 2));
                ldsm4(ah[mi], aS + off);
            }
            uint32_t bh[4][2];
#pragma unroll
            for (int nt = 0; nt < 2; nt++) {
                uint32_t off = swz((uint32_t)((bRowIn + nt * 16) * 128 +
                                              (kb + bKIn) * 2));
                uint32_t r[4];
                ldsm4(r, bS + off);
                bh[nt * 2][0] = r[0]; bh[nt * 2][1] = r[1];
                bh[nt * 2 + 1][0] = r[2]; bh[nt * 2 + 1][1] = r[3];
            }
#pragma unroll
            for (int mi = 0; mi < 4; mi++)
#pragma unroll
                for (int ni = 0; ni < 4; ni++)
                    mma16816(acc[mi][ni], ah[mi], bh[ni]);
        }

        __syncthreads();
        if (c + NSTAGE < NCHUNK)
            load_stage(sbase, tid, rowBase, colBase, (c + NSTAGE) * BK);
        bufc = (bufc == NSTAGE - 1) ? 0 : bufc + 1;
    }
    __syncthreads();   // safe to reuse smem for scan partials

    // ------------- epilogue: gates + stores + fused segment summary -------------
    float2* part = reinterpret_cast<float2*>(smem);   // [wM][wN][ni][half][lane]

    const int rBase = rowBase + warpM * 64 + (lid >> 2);
    const int oLane = (lid & 3);

#pragma unroll
    for (int ni = 0; ni < 4; ni++) {
        const int o = ((colBase + warpN * 32 + ni * 8) >> 1) + oLane;
        const float fb = __ldg(bias + N_OUT + o);
        float F0 = 1.0f, U0 = 0.0f, F1 = 1.0f, U1 = 0.0f;
#pragma unroll
        for (int mi = 0; mi < 4; mi++) {
            const int r0 = rBase + mi * 16;
            const int r1 = r0 + 8;
            float f0 = 1.0f / (1.0f + __expf(-(acc[mi][ni][1] + fb)));
            float u0 = acc[mi][ni][0] * (1.0f - f0);
            float f1 = 1.0f / (1.0f + __expf(-(acc[mi][ni][3] + fb)));
            float u1 = acc[mi][ni][2] * (1.0f - f1);
            u0_out[(size_t)r0 * N_OUT + o] = u0;
            f_out [(size_t)r0 * N_OUT + o] = f0;
            u0_out[(size_t)r1 * N_OUT + o] = u1;
            f_out [(size_t)r1 * N_OUT + o] = f1;
            U0 = fmaf(U0, f0, u0); F0 *= f0;
            U1 = fmaf(U1, f1, u1); F1 *= f1;
        }
        int base = ((warpM * 4 + warpN) * 4 + ni) * 64;
        part[base + lid]      = make_float2(F0, U0);
        part[base + 32 + lid] = make_float2(F1, U1);
    }
    __syncthreads();

    // combine partials across warpM (l-order) and write g_F/g_U
    const int seg = blockIdx.y;
#pragma unroll
    for (int it = 0; it < 2; it++) {
        int item = tid + it * 512;              // [wN(2b)|ni(2b)|half(1b)|lane(5b)]
        int iwN   = item >> 8;
        int ini   = (item >> 6) & 3;
        int ihalf = (item >> 5) & 1;
        int ilane = item & 31;
        float F = 1.0f, U = 0.0f;
#pragma unroll
        for (int w = 0; w < 4; w++) {
            float2 p = part[(((w * 4 + iwN) * 4 + ini) * 2 + ihalf) * 32 + ilane];
            U = fmaf(U, p.x, p.y);
            F *= p.x;
        }
        int b = (ilane >> 2) + ihalf * 8;
        int j = b * N_OUT + blockIdx.x * 64 + iwN * 16 + ini * 4 + (ilane & 3);
        g_F[seg][j] = F;
        g_U[seg][j] = U;
    }
}

// ---------------------------------------------------------------------------
// Phase B: warp-parallel affine scan over 128 segments.
// One warp per chain; block handles 8 chains; smem-staged coalesced I/O.
// Compose (applied a then b): (Fa,Ua) then (Fb,Ub) -> (Fa*Fb, Ua*Fb+Ub).
// ---------------------------------------------------------------------------
__global__ __launch_bounds__(256)
void scan_phaseB(const float* __restrict__ c_init,
                 float* __restrict__ c_final) {
    __shared__ float sF[8][SEGS];   // [chain-in-block][segment]
    __shared__ float sU[8][SEGS];
    __shared__ float sC[8][SEGS];

    const int tid = threadIdx.x;
    const int jBase = blockIdx.x * 8;

    // coalesced load: idx -> s = idx>>3 (row), jj = idx&7
#pragma unroll
    for (int it = 0; it < 4; it++) {
        int idx = it * 256 + tid;
        int s = idx >> 3, jj = idx & 7;
        sF[jj][s] = g_F[s][jBase + jj];
        sU[jj][s] = g_U[s][jBase + jj];
    }
    __syncthreads();

    const int w = tid >> 5;        // chain index within block
    const int lane = tid & 31;     // owns segments lane*4 .. lane*4+3
    const int j = jBase + w;

    float4 Fv = *reinterpret_cast<const float4*>(&sF[w][lane * 4]);
    float4 Uv = *reinterpret_cast<const float4*>(&sU[w][lane * 4]);

    // local inclusive compose
    float Pf[4], Pu[4];
    Pf[0] = Fv.x;            Pu[0] = Uv.x;
    Pf[1] = Pf[0] * Fv.y;    Pu[1] = fmaf(Pu[0], Fv.y, Uv.y);
    Pf[2] = Pf[1] * Fv.z;    Pu[2] = fmaf(Pu[1], Fv.z, Uv.z);
    Pf[3] = Pf[2] * Fv.w;    Pu[3] = fmaf(Pu[2], Fv.w, Uv.w);

    // warp inclusive scan of lane totals
    float tf = Pf[3], tu = Pu[3];
#pragma unroll
    for (int d = 1; d < 32; d <<= 1) {
        float of = __shfl_up_sync(0xffffffffu, tf, d);
        float ou = __shfl_up_sync(0xffffffffu, tu, d);
        if (lane >= d) {
            tu = fmaf(ou, tf, tu);   // earlier (of,ou) then current (tf,tu)
            tf = of * tf;
        }
    }
    // exclusive prefix for this lane = inclusive of lane-1
    float ef = __shfl_up_sync(0xffffffffu, tf, 1);
    float eu = __shfl_up_sync(0xffffffffu, tu, 1);
    if (lane == 0) { ef = 1.0f; eu = 0.0f; }

    const float c0 = c_init[j];
    float4 cin;
    cin.x = fmaf(c0, ef, eu);
    cin.y = fmaf(c0, ef * Pf[0], fmaf(eu, Pf[0], Pu[0]));
    cin.z = fmaf(c0, ef * Pf[1], fmaf(eu, Pf[1], Pu[1]));
    cin.w = fmaf(c0, ef * Pf[2], fmaf(eu, Pf[2], Pu[2]));
    *reinterpret_cast<float4*>(&sC[w][lane * 4]) = cin;

    if (lane == 31)
        c_final[j] = fmaf(c0, tf, tu);

    __syncthreads();
    // coalesced store of Cin
#pragma unroll
    for (int it = 0; it < 2; it++) {
        int idx = it * 256 + tid;
        int s = idx >> 3, jj = idx & 7;
        g_Cin[s][jBase + jj]        = sC[jj][s];
        g_Cin[s + 64][jBase + jj]   = sC[jj][s + 64];
    }
}

// ---------------------------------------------------------------------------
// Phase C: replay. 128 segments x 16 steps.
// ---------------------------------------------------------------------------
__global__ __launch_bounds__(256)
void scan_phaseC(float* __restrict__ cs,
                 const float* __restrict__ f) {
    const int j = blockIdx.x * 256 + threadIdx.x;
    const int s = blockIdx.y;
    size_t idx = (size_t)s * SEG_LEN * NCH + j;
    float c = g_Cin[s][j];
#pragma unroll
    for (int t = 0; t < SEG_LEN; t++) {
        float ft = f[idx];
        float ut = cs[idx];
        c = fmaf(c, ft, ut);
        cs[idx] = c;
        idx += NCH;
    }
}

// ---------------------------------------------------------------------------
extern "C" void kernel_launch(void* const* d_in, const int* in_sizes, int n_in,
                              void* d_out, int out_size)
{
    const float* input  = (const float*)d_in[0];
    const float* c_init = (const float*)d_in[1];
    const float* weight = (const float*)d_in[2];
    const float* bias   = (const float*)d_in[3];

    float* out    = (float*)d_out;
    float* cs     = out + CS_OFF;
    float* cfin   = out + CFINAL_OFF;
    float* forget = out + FORGET_OFF;

    cudaFuncSetAttribute(gemm_mma_kernel,
                         cudaFuncAttributeMaxDynamicSharedMemorySize, SMEM_TOTAL);

    convert_a_kernel<<<(M_ROWS * K_DIM) / (256 * 8), 256>>>(input);
    convert_b_kernel<<<dim3(N_COLS / 32, K_DIM / 32), 256>>>(weight);

    dim3 grid(N_COLS / 128, M_ROWS / 256);   // (16, 128) — blockIdx.y = segment
    gemm_mma_kernel<<<grid, 512, SMEM_TOTAL>>>(bias, cs, forget);

    scan_phaseB<<<NCH / 8, 256>>>(c_init, cfin);   // 2048 blocks, 8 chains each
    dim3 cgrid(NCH / 256, SEGS);
    scan_phaseC<<<cgrid, 256>>>(cs, forget);
}

// round 10
// speedup vs baseline: 1.0933x; 1.0033x over previous
#include <cuda_runtime.h>
#include <cuda_fp16.h>
#include <stdint.h>

#define L_SEQ   2048
#define BATCH   16
#define N_IN    1024
#define N_OUT   1024
#define M_ROWS  (L_SEQ * BATCH)      // 32768
#define N_COLS  (2 * N_OUT)          // 2048
#define K_DIM   1024
#define NCH     (BATCH * N_OUT)      // 16384 chains

#define CS_OFF      0
#define CFINAL_OFF  (M_ROWS * N_OUT)
#define FORGET_OFF  (M_ROWS * N_OUT + BATCH * N_OUT)

// fp16 operands. A: [32768,1024] k-contig. B = fp16(W^T): [2048,1024].
__device__ __half g_Ah[(size_t)M_ROWS * K_DIM];
__device__ __half g_Bh[(size_t)N_COLS * K_DIM];

// scan scratch. One segment = one GEMM M-tile = 16 l-steps.
#define SEGS 128
#define SEG_LEN (L_SEQ / SEGS)       // 16
__device__ float g_F  [SEGS][NCH];
__device__ float g_U  [SEGS][NCH];
__device__ float g_Cin[SEGS][NCH];

// ---------------------------------------------------------------------------
__device__ __forceinline__ uint32_t s2u(const void* p) {
    uint32_t r;
    asm("{ .reg .u64 t; cvta.to.shared.u64 t, %1; cvt.u32.u64 %0, t; }"
        : "=r"(r) : "l"(p));
    return r;
}
__device__ __forceinline__ void cp16(uint32_t saddr, const void* gptr) {
    uint64_t g = (uint64_t)__cvta_generic_to_global(gptr);
    asm volatile("cp.async.cg.shared.global [%0], [%1], 16;"
                 :: "r"(saddr), "l"(g) : "memory");
}
__device__ __forceinline__ void cp_commit() {
    asm volatile("cp.async.commit_group;" ::: "memory");
}
template <int N>
__device__ __forceinline__ void cp_wait() {
    asm volatile("cp.async.wait_group %0;" :: "n"(N) : "memory");
}
__device__ __forceinline__ void ldsm4(uint32_t* r, uint32_t addr) {
    asm volatile("ldmatrix.sync.aligned.m8n8.x4.shared.b16 {%0,%1,%2,%3}, [%4];"
                 : "=r"(r[0]), "=r"(r[1]), "=r"(r[2]), "=r"(r[3]) : "r"(addr));
}
__device__ __forceinline__ void mma16816(float* d, const uint32_t* a, const uint32_t* b) {
    asm volatile(
        "mma.sync.aligned.m16n8k16.row.col.f32.f16.f16.f32 "
        "{%0,%1,%2,%3}, {%4,%5,%6,%7}, {%8,%9}, {%0,%1,%2,%3};"
        : "+f"(d[0]), "+f"(d[1]), "+f"(d[2]), "+f"(d[3])
        : "r"(a[0]), "r"(a[1]), "r"(a[2]), "r"(a[3]), "r"(b[0]), "r"(b[1]));
}
__device__ __forceinline__ uint32_t swz(uint32_t off) {
    return off ^ ((off >> 3) & 0x70);
}

// ---------------------------------------------------------------------------
// Operand prep
// ---------------------------------------------------------------------------
__global__ __launch_bounds__(256)
void convert_a_kernel(const float* __restrict__ A) {
    size_t i = ((size_t)blockIdx.x * 256 + threadIdx.x) * 8;
    float4 v0 = *reinterpret_cast<const float4*>(A + i);
    float4 v1 = *reinterpret_cast<const float4*>(A + i + 4);
    __half2 h0 = __floats2half2_rn(v0.x, v0.y);
    __half2 h1 = __floats2half2_rn(v0.z, v0.w);
    __half2 h2 = __floats2half2_rn(v1.x, v1.y);
    __half2 h3 = __floats2half2_rn(v1.z, v1.w);
    uint4 pk;
    pk.x = *reinterpret_cast<uint32_t*>(&h0);
    pk.y = *reinterpret_cast<uint32_t*>(&h1);
    pk.z = *reinterpret_cast<uint32_t*>(&h2);
    pk.w = *reinterpret_cast<uint32_t*>(&h3);
    *reinterpret_cast<uint4*>(g_Ah + i) = pk;
}

__global__ __launch_bounds__(256)
void convert_b_kernel(const float* __restrict__ W) {
    __shared__ float t[32][33];
    int n0 = blockIdx.x * 32;
    int k0 = blockIdx.y * 32;
    int tx = threadIdx.x & 31;
    int ty = threadIdx.x >> 5;
#pragma unroll
    for (int i = 0; i < 4; i++)
        t[ty + i * 8][tx] = W[(size_t)(k0 + ty + i * 8) * N_COLS + n0 + tx];
    __syncthreads();
#pragma unroll
    for (int i = 0; i < 4; i++) {
        int n = ty + i * 8;
        g_Bh[(size_t)(n0 + n) * K_DIM + k0 + tx] = __float2half_rn(t[tx][n]);
    }
}

// ---------------------------------------------------------------------------
// GEMM: BM=256, BN=128, BK=64, 512 threads = 16 warps (4M x 4N),
// warp tile 64x32. C = Ah * Bh, fp32 accum. 4-stage cp.async pipeline,
// single barrier per chunk, loads issued before compute.
// Epilogue: gates + per-segment scan summaries (fused phaseA).
// ---------------------------------------------------------------------------
#define BK 64
#define OFF_A 0
#define OFF_B 32768
#define STAGE_BYTES 49152
#define NSTAGE 4
#define SMEM_TOTAL (NSTAGE * STAGE_BYTES)   // 196608
#define NCHUNK (K_DIM / BK)                 // 16

__device__ __forceinline__ void load_stage(uint32_t sbase, int tid,
                                           int rowBase, int colBase, int k0) {
    const char* ah = reinterpret_cast<const char*>(g_Ah);
    const char* bh = reinterpret_cast<const char*>(g_Bh);
#pragma unroll
    for (int i = 0; i < 4; i++) {               // A: 256 rows x 8 x 16B
        int idx = i * 512 + tid;
        int row = idx >> 3, c = idx & 7;
        uint32_t so = swz((uint32_t)(row * 128 + c * 16));
        size_t go = ((size_t)(rowBase + row) * K_DIM + k0) * 2 + c * 16;
        cp16(sbase + OFF_A + so, ah + go);
    }
#pragma unroll
    for (int i = 0; i < 2; i++) {               // B: 128 rows x 8 x 16B
        int idx = i * 512 + tid;
        int row = idx >> 3, c = idx & 7;
        uint32_t so = swz((uint32_t)(row * 128 + c * 16));
        size_t go = ((size_t)(colBase + row) * K_DIM + k0) * 2 + c * 16;
        cp16(sbase + OFF_B + so, bh + go);
    }
    cp_commit();
}

__global__ __launch_bounds__(512, 1)
void gemm_mma_kernel(const float* __restrict__ bias,
                     float* __restrict__ u0_out,
                     float* __restrict__ f_out) {
    extern __shared__ char smem[];
    const uint32_t sb = s2u(smem);
    const int tid = threadIdx.x;
    const int lid = tid & 31;
    const int wid = tid >> 5;            // 0..15
    const int warpM = wid & 3;           // 4 x 64-row slices
    const int warpN = wid >> 2;          // 4 x 32-col slices
    const int colBase = blockIdx.x * 128;
    const int rowBase = blockIdx.y * 256;

    float acc[4][4][4];
#pragma unroll
    for (int mi = 0; mi < 4; mi++)
#pragma unroll
        for (int ni = 0; ni < 4; ni++)
#pragma unroll
            for (int e = 0; e < 4; e++)
                acc[mi][ni][e] = 0.0f;

    // prologue: fill all 4 stages (chunks 0..3)
#pragma unroll
    for (int s = 0; s < NSTAGE; s++)
        load_stage(sb + s * STAGE_BYTES, tid, rowBase, colBase, s * BK);

    const int aRowIn = warpM * 64 + (lid & 15);
    const int aKIn   = (lid >> 4) * 8;
    const int bRowIn = warpN * 32 + (lid & 7) + ((lid >> 4) & 1) * 8;
    const int bKIn   = ((lid >> 3) & 1) * 8;

    for (int c = 0; c < NCHUNK; c++) {
        // retire chunk c's group. Group ledger: at top of iter c the last
        // committed group is c+2 (c>=1) / 3 (c==0); issues stop after c==12.
        if (c == 0)       cp_wait<3>();
        else if (c <= 13) cp_wait<2>();
        else if (c == 14) cp_wait<1>();
        else              cp_wait<0>();
        // ONE barrier: chunk c data visible to all; buffer (c-1)&3 fully
        // consumed by all warps (its reads happened in iter c-1).
        __syncthreads();

        // issue next load FIRST: chunk c+3 -> buffer (c-1)&3
        if (c >= 1 && c + 3 < NCHUNK)
            load_stage(sb + ((c - 1) & 3) * STAGE_BYTES, tid,
                       rowBase, colBase, (c + 3) * BK);

        const uint32_t sbase = sb + (c & 3) * STAGE_BYTES;
        const uint32_t aS = sbase + OFF_A;
        const uint32_t bS = sbase + OFF_B;

#pragma unroll
        for (int ks = 0; ks < 4; ks++) {
            const int kb = ks * 16;
            uint32_t ah[4][4];
#pragma unroll
            for (int mi = 0; mi < 4; mi++) {
                uint32_t off = swz((uint32_t)((aRowIn + mi * 16) * 128 +
                                              (kb + aKIn) * 2));
                ldsm4(ah[mi], aS + off);
            }
            uint32_t bh[4][2];
#pragma unroll
            for (int nt = 0; nt < 2; nt++) {
                uint32_t off = swz((uint32_t)((bRowIn + nt * 16) * 128 +
                                              (kb + bKIn) * 2));
                uint32_t r[4];
                ldsm4(r, bS + off);
                bh[nt * 2][0] = r[0]; bh[nt * 2][1] = r[1];
                bh[nt * 2 + 1][0] = r[2]; bh[nt * 2 + 1][1] = r[3];
            }
#pragma unroll
            for (int mi = 0; mi < 4; mi++)
#pragma unroll
                for (int ni = 0; ni < 4; ni++)
                    mma16816(acc[mi][ni], ah[mi], bh[ni]);
        }
    }
    __syncthreads();   // safe to reuse smem for scan partials

    // ------------- epilogue: gates + stores + fused segment summary -------------
    float2* part = reinterpret_cast<float2*>(smem);   // [wM][wN][ni][half][lane]

    const int rBase = rowBase + warpM * 64 + (lid >> 2);
    const int oLane = (lid & 3);

#pragma unroll
    for (int ni = 0; ni < 4; ni++) {
        const int o = ((colBase + warpN * 32 + ni * 8) >> 1) + oLane;
        const float fb = __ldg(bias + N_OUT + o);
        float F0 = 1.0f, U0 = 0.0f, F1 = 1.0f, U1 = 0.0f;
#pragma unroll
        for (int mi = 0; mi < 4; mi++) {
            const int r0 = rBase + mi * 16;
            const int r1 = r0 + 8;
            float f0 = 1.0f / (1.0f + __expf(-(acc[mi][ni][1] + fb)));
            float u0 = acc[mi][ni][0] * (1.0f - f0);
            float f1 = 1.0f / (1.0f + __expf(-(acc[mi][ni][3] + fb)));
            float u1 = acc[mi][ni][2] * (1.0f - f1);
            u0_out[(size_t)r0 * N_OUT + o] = u0;
            f_out [(size_t)r0 * N_OUT + o] = f0;
            u0_out[(size_t)r1 * N_OUT + o] = u1;
            f_out [(size_t)r1 * N_OUT + o] = f1;
            U0 = fmaf(U0, f0, u0); F0 *= f0;
            U1 = fmaf(U1, f1, u1); F1 *= f1;
        }
        int base = ((warpM * 4 + warpN) * 4 + ni) * 64;
        part[base + lid]      = make_float2(F0, U0);
        part[base + 32 + lid] = make_float2(F1, U1);
    }
    __syncthreads();

    // combine partials across warpM (l-order) and write g_F/g_U
    const int seg = blockIdx.y;
#pragma unroll
    for (int it = 0; it < 2; it++) {
        int item = tid + it * 512;              // [wN(2b)|ni(2b)|half(1b)|lane(5b)]
        int iwN   = item >> 8;
        int ini   = (item >> 6) & 3;
        int ihalf = (item >> 5) & 1;
        int ilane = item & 31;
        float F = 1.0f, U = 0.0f;
#pragma unroll
        for (int w = 0; w < 4; w++) {
            float2 p = part[(((w * 4 + iwN) * 4 + ini) * 2 + ihalf) * 32 + ilane];
            U = fmaf(U, p.x, p.y);
            F *= p.x;
        }
        int b = (ilane >> 2) + ihalf * 8;
        int j = b * N_OUT + blockIdx.x * 64 + iwN * 16 + ini * 4 + (ilane & 3);
        g_F[seg][j] = F;
        g_U[seg][j] = U;
    }
}

// ---------------------------------------------------------------------------
// Phase B: warp-parallel affine scan over 128 segments.
// ---------------------------------------------------------------------------
__global__ __launch_bounds__(256)
void scan_phaseB(const float* __restrict__ c_init,
                 float* __restrict__ c_final) {
    __shared__ float sF[8][SEGS];
    __shared__ float sU[8][SEGS];
    __shared__ float sC[8][SEGS];

    const int tid = threadIdx.x;
    const int jBase = blockIdx.x * 8;

#pragma unroll
    for (int it = 0; it < 4; it++) {
        int idx = it * 256 + tid;
        int s = idx >> 3, jj = idx & 7;
        sF[jj][s] = g_F[s][jBase + jj];
        sU[jj][s] = g_U[s][jBase + jj];
    }
    __syncthreads();

    const int w = tid >> 5;
    const int lane = tid & 31;
    const int j = jBase + w;

    float4 Fv = *reinterpret_cast<const float4*>(&sF[w][lane * 4]);
    float4 Uv = *reinterpret_cast<const float4*>(&sU[w][lane * 4]);

    float Pf[4], Pu[4];
    Pf[0] = Fv.x;            Pu[0] = Uv.x;
    Pf[1] = Pf[0] * Fv.y;    Pu[1] = fmaf(Pu[0], Fv.y, Uv.y);
    Pf[2] = Pf[1] * Fv.z;    Pu[2] = fmaf(Pu[1], Fv.z, Uv.z);
    Pf[3] = Pf[2] * Fv.w;    Pu[3] = fmaf(Pu[2], Fv.w, Uv.w);

    float tf = Pf[3], tu = Pu[3];
#pragma unroll
    for (int d = 1; d < 32; d <<= 1) {
        float of = __shfl_up_sync(0xffffffffu, tf, d);
        float ou = __shfl_up_sync(0xffffffffu, tu, d);
        if (lane >= d) {
            tu = fmaf(ou, tf, tu);
            tf = of * tf;
        }
    }
    float ef = __shfl_up_sync(0xffffffffu, tf, 1);
    float eu = __shfl_up_sync(0xffffffffu, tu, 1);
    if (lane == 0) { ef = 1.0f; eu = 0.0f; }

    const float c0 = c_init[j];
    float4 cin;
    cin.x = fmaf(c0, ef, eu);
    cin.y = fmaf(c0, ef * Pf[0], fmaf(eu, Pf[0], Pu[0]));
    cin.z = fmaf(c0, ef * Pf[1], fmaf(eu, Pf[1], Pu[1]));
    cin.w = fmaf(c0, ef * Pf[2], fmaf(eu, Pf[2], Pu[2]));
    *reinterpret_cast<float4*>(&sC[w][lane * 4]) = cin;

    if (lane == 31)
        c_final[j] = fmaf(c0, tf, tu);

    __syncthreads();
#pragma unroll
    for (int it = 0; it < 2; it++) {
        int idx = it * 256 + tid;
        int s = idx >> 3, jj = idx & 7;
        g_Cin[s][jBase + jj]        = sC[jj][s];
        g_Cin[s + 64][jBase + jj]   = sC[jj][s + 64];
    }
}

// ---------------------------------------------------------------------------
// Phase C: replay. 128 segments x 16 steps.
// ---------------------------------------------------------------------------
__global__ __launch_bounds__(256)
void scan_phaseC(float* __restrict__ cs,
                 const float* __restrict__ f) {
    const int j = blockIdx.x * 256 + threadIdx.x;
    const int s = blockIdx.y;
    size_t idx = (size_t)s * SEG_LEN * NCH + j;
    float c = g_Cin[s][j];
#pragma unroll
    for (int t = 0; t < SEG_LEN; t++) {
        float ft = f[idx];
        float ut = cs[idx];
        c = fmaf(c, ft, ut);
        cs[idx] = c;
        idx += NCH;
    }
}

// ---------------------------------------------------------------------------
extern "C" void kernel_launch(void* const* d_in, const int* in_sizes, int n_in,
                              void* d_out, int out_size)
{
    const float* input  = (const float*)d_in[0];
    const float* c_init = (const float*)d_in[1];
    const float* weight = (const float*)d_in[2];
    const float* bias   = (const float*)d_in[3];

    float* out    = (float*)d_out;
    float* cs     = out + CS_OFF;
    float* cfin   = out + CFINAL_OFF;
    float* forget = out + FORGET_OFF;

    cudaFuncSetAttribute(gemm_mma_kernel,
                         cudaFuncAttributeMaxDynamicSharedMemorySize, SMEM_TOTAL);

    convert_a_kernel<<<(M_ROWS * K_DIM) / (256 * 8), 256>>>(input);
    convert_b_kernel<<<dim3(N_COLS / 32, K_DIM / 32), 256>>>(weight);

    dim3 grid(N_COLS / 128, M_ROWS / 256);   // (16, 128) — blockIdx.y = segment
    gemm_mma_kernel<<<grid, 512, SMEM_TOTAL>>>(bias, cs, forget);

    scan_phaseB<<<NCH / 8, 256>>>(c_init, cfin);   // 2048 blocks, 8 chains each
    dim3 cgrid(NCH / 256, SEGS);
    scan_phaseC<<<cgrid, 256>>>(cs, forget);
}

// round 11
// speedup vs baseline: 1.2132x; 1.1097x over previous
#include <cuda_runtime.h>
#include <cuda_fp16.h>
#include <stdint.h>

#define L_SEQ   2048
#define BATCH   16
#define N_IN    1024
#define N_OUT   1024
#define M_ROWS  (L_SEQ * BATCH)      // 32768
#define N_COLS  (2 * N_OUT)          // 2048
#define K_DIM   1024
#define NCH     (BATCH * N_OUT)      // 16384 chains

#define CS_OFF      0
#define CFINAL_OFF  (M_ROWS * N_OUT)
#define FORGET_OFF  (M_ROWS * N_OUT + BATCH * N_OUT)

// fp16 operands. A: [32768,1024] k-contig. B = fp16(W^T): [2048,1024].
__device__ __half g_Ah[(size_t)M_ROWS * K_DIM];
__device__ __half g_Bh[(size_t)N_COLS * K_DIM];

// scan scratch. One segment = one GEMM M-tile = 8 l-steps.
#define SEGS 256
#define SEG_LEN (L_SEQ / SEGS)       // 8
__device__ float g_F  [SEGS][NCH];
__device__ float g_U  [SEGS][NCH];
__device__ float g_Cin[SEGS][NCH];

// ---------------------------------------------------------------------------
__device__ __forceinline__ uint32_t s2u(const void* p) {
    uint32_t r;
    asm("{ .reg .u64 t; cvta.to.shared.u64 t, %1; cvt.u32.u64 %0, t; }"
        : "=r"(r) : "l"(p));
    return r;
}
__device__ __forceinline__ void cp16(uint32_t saddr, const void* gptr) {
    uint64_t g = (uint64_t)__cvta_generic_to_global(gptr);
    asm volatile("cp.async.cg.shared.global [%0], [%1], 16;"
                 :: "r"(saddr), "l"(g) : "memory");
}
__device__ __forceinline__ void cp_commit() {
    asm volatile("cp.async.commit_group;" ::: "memory");
}
template <int N>
__device__ __forceinline__ void cp_wait() {
    asm volatile("cp.async.wait_group %0;" :: "n"(N) : "memory");
}
__device__ __forceinline__ void ldsm4(uint32_t* r, uint32_t addr) {
    asm volatile("ldmatrix.sync.aligned.m8n8.x4.shared.b16 {%0,%1,%2,%3}, [%4];"
                 : "=r"(r[0]), "=r"(r[1]), "=r"(r[2]), "=r"(r[3]) : "r"(addr));
}
__device__ __forceinline__ void mma16816(float* d, const uint32_t* a, const uint32_t* b) {
    asm volatile(
        "mma.sync.aligned.m16n8k16.row.col.f32.f16.f16.f32 "
        "{%0,%1,%2,%3}, {%4,%5,%6,%7}, {%8,%9}, {%0,%1,%2,%3};"
        : "+f"(d[0]), "+f"(d[1]), "+f"(d[2]), "+f"(d[3])
        : "r"(a[0]), "r"(a[1]), "r"(a[2]), "r"(a[3]), "r"(b[0]), "r"(b[1]));
}
__device__ __forceinline__ uint32_t swz(uint32_t off) {
    return off ^ ((off >> 3) & 0x70);
}

// ---------------------------------------------------------------------------
// Operand prep
// ---------------------------------------------------------------------------
__global__ __launch_bounds__(256)
void convert_a_kernel(const float* __restrict__ A) {
    size_t i = ((size_t)blockIdx.x * 256 + threadIdx.x) * 8;
    float4 v0 = *reinterpret_cast<const float4*>(A + i);
    float4 v1 = *reinterpret_cast<const float4*>(A + i + 4);
    __half2 h0 = __floats2half2_rn(v0.x, v0.y);
    __half2 h1 = __floats2half2_rn(v0.z, v0.w);
    __half2 h2 = __floats2half2_rn(v1.x, v1.y);
    __half2 h3 = __floats2half2_rn(v1.z, v1.w);
    uint4 pk;
    pk.x = *reinterpret_cast<uint32_t*>(&h0);
    pk.y = *reinterpret_cast<uint32_t*>(&h1);
    pk.z = *reinterpret_cast<uint32_t*>(&h2);
    pk.w = *reinterpret_cast<uint32_t*>(&h3);
    *reinterpret_cast<uint4*>(g_Ah + i) = pk;
}

__global__ __launch_bounds__(256)
void convert_b_kernel(const float* __restrict__ W) {
    __shared__ float t[32][33];
    int n0 = blockIdx.x * 32;
    int k0 = blockIdx.y * 32;
    int tx = threadIdx.x & 31;
    int ty = threadIdx.x >> 5;
#pragma unroll
    for (int i = 0; i < 4; i++)
        t[ty + i * 8][tx] = W[(size_t)(k0 + ty + i * 8) * N_COLS + n0 + tx];
    __syncthreads();
#pragma unroll
    for (int i = 0; i < 4; i++) {
        int n = ty + i * 8;
        g_Bh[(size_t)(n0 + n) * K_DIM + k0 + tx] = __float2half_rn(t[tx][n]);
    }
}

// ---------------------------------------------------------------------------
// GEMM: BM=128, BN=128, BK=64, 256 threads = 8 warps (2M x 4N),
// warp tile 64x32. 3-stage cp.async pipeline, 2 CTAs per SM.
// Epilogue: gates + per-segment scan summaries (fused phaseA, SEG_LEN=8).
// ---------------------------------------------------------------------------
#define BK 64
#define OFF_A 0
#define OFF_B 16384
#define STAGE_BYTES 32768
#define NSTAGE 3
#define SMEM_TOTAL (NSTAGE * STAGE_BYTES)   // 98304
#define NCHUNK (K_DIM / BK)                 // 16

__device__ __forceinline__ void load_stage(uint32_t sbase, int tid,
                                           int rowBase, int colBase, int k0) {
    const char* ah = reinterpret_cast<const char*>(g_Ah);
    const char* bh = reinterpret_cast<const char*>(g_Bh);
#pragma unroll
    for (int i = 0; i < 4; i++) {               // A: 128 rows x 8 x 16B
        int idx = i * 256 + tid;
        int row = idx >> 3, c = idx & 7;
        uint32_t so = swz((uint32_t)(row * 128 + c * 16));
        size_t go = ((size_t)(rowBase + row) * K_DIM + k0) * 2 + c * 16;
        cp16(sbase + OFF_A + so, ah + go);
    }
#pragma unroll
    for (int i = 0; i < 4; i++) {               // B: 128 rows x 8 x 16B
        int idx = i * 256 + tid;
        int row = idx >> 3, c = idx & 7;
        uint32_t so = swz((uint32_t)(row * 128 + c * 16));
        size_t go = ((size_t)(colBase + row) * K_DIM + k0) * 2 + c * 16;
        cp16(sbase + OFF_B + so, bh + go);
    }
    cp_commit();
}

__global__ __launch_bounds__(256, 2)
void gemm_mma_kernel(const float* __restrict__ bias,
                     float* __restrict__ u0_out,
                     float* __restrict__ f_out) {
    extern __shared__ char smem[];
    const uint32_t sb = s2u(smem);
    const int tid = threadIdx.x;
    const int lid = tid & 31;
    const int wid = tid >> 5;            // 0..7
    const int warpM = wid & 1;           // 2 x 64-row slices
    const int warpN = wid >> 1;          // 4 x 32-col slices
    const int colBase = blockIdx.x * 128;
    const int rowBase = blockIdx.y * 128;

    float acc[4][4][4];
#pragma unroll
    for (int mi = 0; mi < 4; mi++)
#pragma unroll
        for (int ni = 0; ni < 4; ni++)
#pragma unroll
            for (int e = 0; e < 4; e++)
                acc[mi][ni][e] = 0.0f;

    // prologue: fill 3 stages (chunks 0..2)
#pragma unroll
    for (int s = 0; s < NSTAGE; s++)
        load_stage(sb + s * STAGE_BYTES, tid, rowBase, colBase, s * BK);

    const int aRowIn = warpM * 64 + (lid & 15);
    const int aKIn   = (lid >> 4) * 8;
    const int bRowIn = warpN * 32 + (lid & 7) + ((lid >> 4) & 1) * 8;
    const int bKIn   = ((lid >> 3) & 1) * 8;

    for (int c = 0; c < NCHUNK; c++) {
        // ledger: pending before wait = {c,c+1,c+2}@c==0, {c,c+1} for 1<=c<=14,
        // {15}@c==15. Retire chunk c.
        if (c == 0)       cp_wait<2>();
        else if (c < 15)  cp_wait<1>();
        else              cp_wait<0>();
        __syncthreads();   // data visible + buffer (c-1)%3 drained by all warps

        // issue chunk c+2 into buffer (c+2)%3 == (c-1)%3 (free after barrier)
        if (c >= 1 && c + 2 < NCHUNK)
            load_stage(sb + ((c + 2) % 3) * STAGE_BYTES, tid,
                       rowBase, colBase, (c + 2) * BK);

        const uint32_t sbase = sb + (c % 3) * STAGE_BYTES;
        const uint32_t aS = sbase + OFF_A;
        const uint32_t bS = sbase + OFF_B;

#pragma unroll
        for (int ks = 0; ks < 4; ks++) {
            const int kb = ks * 16;
            uint32_t ah[4][4];
#pragma unroll
            for (int mi = 0; mi < 4; mi++) {
                uint32_t off = swz((uint32_t)((aRowIn + mi * 16) * 128 +
                                              (kb + aKIn) * 2));
                ldsm4(ah[mi], aS + off);
            }
            uint32_t bh[4][2];
#pragma unroll
            for (int nt = 0; nt < 2; nt++) {
                uint32_t off = swz((uint32_t)((bRowIn + nt * 16) * 128 +
                                              (kb + bKIn) * 2));
                uint32_t r[4];
                ldsm4(r, bS + off);
                bh[nt * 2][0] = r[0]; bh[nt * 2][1] = r[1];
                bh[nt * 2 + 1][0] = r[2]; bh[nt * 2 + 1][1] = r[3];
            }
#pragma unroll
            for (int mi = 0; mi < 4; mi++)
#pragma unroll
                for (int ni = 0; ni < 4; ni++)
                    mma16816(acc[mi][ni], ah[mi], bh[ni]);
        }
    }
    __syncthreads();   // safe to reuse smem for scan partials

    // ------------- epilogue: gates + stores + fused segment summary -------------
    // tile row r: l_local = r>>4 (0..7), b = r&15. Lane chain fixed per (ni,half);
    // l_local = warpM*4 + mi. Combine across 2 warpM warps via smem.
    float2* part = reinterpret_cast<float2*>(smem);   // [wM(2)][wN(4)][ni(4)][half(2)][lane(32)]

    const int rBase = rowBase + warpM * 64 + (lid >> 2);
    const int oLane = (lid & 3);

#pragma unroll
    for (int ni = 0; ni < 4; ni++) {
        const int o = ((colBase + warpN * 32 + ni * 8) >> 1) + oLane;
        const float fb = __ldg(bias + N_OUT + o);
        float F0 = 1.0f, U0 = 0.0f, F1 = 1.0f, U1 = 0.0f;
#pragma unroll
        for (int mi = 0; mi < 4; mi++) {
            const int r0 = rBase + mi * 16;
            const int r1 = r0 + 8;
            float f0 = 1.0f / (1.0f + __expf(-(acc[mi][ni][1] + fb)));
            float u0 = acc[mi][ni][0] * (1.0f - f0);
            float f1 = 1.0f / (1.0f + __expf(-(acc[mi][ni][3] + fb)));
            float u1 = acc[mi][ni][2] * (1.0f - f1);
            u0_out[(size_t)r0 * N_OUT + o] = u0;
            f_out [(size_t)r0 * N_OUT + o] = f0;
            u0_out[(size_t)r1 * N_OUT + o] = u1;
            f_out [(size_t)r1 * N_OUT + o] = f1;
            U0 = fmaf(U0, f0, u0); F0 *= f0;
            U1 = fmaf(U1, f1, u1); F1 *= f1;
        }
        int base = ((warpM * 4 + warpN) * 4 + ni) * 64;
        part[base + lid]      = make_float2(F0, U0);
        part[base + 32 + lid] = make_float2(F1, U1);
    }
    __syncthreads();

    // combine partials across warpM (l-order) and write g_F/g_U
    const int seg = blockIdx.y;
#pragma unroll
    for (int it = 0; it < 4; it++) {
        int item = tid + it * 256;              // [wN(2b)|ni(2b)|half(1b)|lane(5b)]
        int iwN   = item >> 8;
        int ini   = (item >> 6) & 3;
        int ihalf = (item >> 5) & 1;
        int ilane = item & 31;
        float F = 1.0f, U = 0.0f;
#pragma unroll
        for (int w = 0; w < 2; w++) {
            float2 p = part[(((w * 4 + iwN) * 4 + ini) * 2 + ihalf) * 32 + ilane];
            U = fmaf(U, p.x, p.y);
            F *= p.x;
        }
        int b = (ilane >> 2) + ihalf * 8;
        int j = b * N_OUT + blockIdx.x * 64 + iwN * 16 + ini * 4 + (ilane & 3);
        g_F[seg][j] = F;
        g_U[seg][j] = U;
    }
}

// ---------------------------------------------------------------------------
// Phase B: warp-parallel affine scan over 256 segments.
// One warp per chain (lane owns 8 segments); 8 chains per block.
// ---------------------------------------------------------------------------
__global__ __launch_bounds__(256)
void scan_phaseB(const float* __restrict__ c_init,
                 float* __restrict__ c_final) {
    __shared__ float sF[8][SEGS];
    __shared__ float sU[8][SEGS];
    __shared__ float sC[8][SEGS];

    const int tid = threadIdx.x;
    const int jBase = blockIdx.x * 8;

#pragma unroll
    for (int it = 0; it < 8; it++) {
        int idx = it * 256 + tid;
        int s = idx >> 3, jj = idx & 7;
        sF[jj][s] = g_F[s][jBase + jj];
        sU[jj][s] = g_U[s][jBase + jj];
    }
    __syncthreads();

    const int w = tid >> 5;
    const int lane = tid & 31;
    const int j = jBase + w;

    float Pf[8], Pu[8];
#pragma unroll
    for (int k = 0; k < 8; k++) {
        float Fk = sF[w][lane * 8 + k];
        float Uk = sU[w][lane * 8 + k];
        if (k == 0) { Pf[0] = Fk; Pu[0] = Uk; }
        else        { Pf[k] = Pf[k - 1] * Fk; Pu[k] = fmaf(Pu[k - 1], Fk, Uk); }
    }

    float tf = Pf[7], tu = Pu[7];
#pragma unroll
    for (int d = 1; d < 32; d <<= 1) {
        float of = __shfl_up_sync(0xffffffffu, tf, d);
        float ou = __shfl_up_sync(0xffffffffu, tu, d);
        if (lane >= d) {
            tu = fmaf(ou, tf, tu);
            tf = of * tf;
        }
    }
    float ef = __shfl_up_sync(0xffffffffu, tf, 1);
    float eu = __shfl_up_sync(0xffffffffu, tu, 1);
    if (lane == 0) { ef = 1.0f; eu = 0.0f; }

    const float c0 = c_init[j];
    sC[w][lane * 8] = fmaf(c0, ef, eu);
#pragma unroll
    for (int k = 1; k < 8; k++)
        sC[w][lane * 8 + k] = fmaf(c0, ef * Pf[k - 1], fmaf(eu, Pf[k - 1], Pu[k - 1]));

    if (lane == 31)
        c_final[j] = fmaf(c0, tf, tu);

    __syncthreads();
#pragma unroll
    for (int it = 0; it < 8; it++) {
        int idx = it * 256 + tid;
        int s = idx >> 3, jj = idx & 7;
        g_Cin[s][jBase + jj] = sC[jj][s];
    }
}

// ---------------------------------------------------------------------------
// Phase C: replay. 256 segments x 8 steps.
// ---------------------------------------------------------------------------
__global__ __launch_bounds__(256)
void scan_phaseC(float* __restrict__ cs,
                 const float* __restrict__ f) {
    const int j = blockIdx.x * 256 + threadIdx.x;
    const int s = blockIdx.y;
    size_t idx = (size_t)s * SEG_LEN * NCH + j;
    float c = g_Cin[s][j];
#pragma unroll
    for (int t = 0; t < SEG_LEN; t++) {
        float ft = f[idx];
        float ut = cs[idx];
        c = fmaf(c, ft, ut);
        cs[idx] = c;
        idx += NCH;
    }
}

// ---------------------------------------------------------------------------
extern "C" void kernel_launch(void* const* d_in, const int* in_sizes, int n_in,
                              void* d_out, int out_size)
{
    const float* input  = (const float*)d_in[0];
    const float* c_init = (const float*)d_in[1];
    const float* weight = (const float*)d_in[2];
    const float* bias   = (const float*)d_in[3];

    float* out    = (float*)d_out;
    float* cs     = out + CS_OFF;
    float* cfin   = out + CFINAL_OFF;
    float* forget = out + FORGET_OFF;

    cudaFuncSetAttribute(gemm_mma_kernel,
                         cudaFuncAttributeMaxDynamicSharedMemorySize, SMEM_TOTAL);

    convert_a_kernel<<<(M_ROWS * K_DIM) / (256 * 8), 256>>>(input);
    convert_b_kernel<<<dim3(N_COLS / 32, K_DIM / 32), 256>>>(weight);

    dim3 grid(N_COLS / 128, M_ROWS / 128);   // (16, 256) — blockIdx.y = segment
    gemm_mma_kernel<<<grid, 256, SMEM_TOTAL>>>(bias, cs, forget);

    scan_phaseB<<<NCH / 8, 256>>>(c_init, cfin);   // 2048 blocks, 8 chains each
    dim3 cgrid(NCH / 256, SEGS);
    scan_phaseC<<<cgrid, 256>>>(cs, forget);
}

// round 13
// speedup vs baseline: 1.2538x; 1.0335x over previous
#include <cuda_runtime.h>
#include <cuda_fp16.h>
#include <stdint.h>

#define L_SEQ   2048
#define BATCH   16
#define N_IN    1024
#define N_OUT   1024
#define M_ROWS  (L_SEQ * BATCH)      // 32768
#define N_COLS  (2 * N_OUT)          // 2048
#define K_DIM   1024
#define NCH     (BATCH * N_OUT)      // 16384 chains

#define CS_OFF      0
#define CFINAL_OFF  (M_ROWS * N_OUT)
#define FORGET_OFF  (M_ROWS * N_OUT + BATCH * N_OUT)

// fp16 operands. A: [32768,1024] k-contig. B = fp16(W^T): [2048,1024].
__device__ __half g_Ah[(size_t)M_ROWS * K_DIM];
__device__ __half g_Bh[(size_t)N_COLS * K_DIM];

// scan scratch. One segment = one GEMM M-tile = 8 l-steps.
#define SEGS 256
#define SEG_LEN (L_SEQ / SEGS)       // 8
__device__ float g_F  [SEGS][NCH];
__device__ float g_U  [SEGS][NCH];
__device__ float g_Cin[SEGS][NCH];

// ---------------------------------------------------------------------------
__device__ __forceinline__ uint32_t s2u(const void* p) {
    uint32_t r;
    asm("{ .reg .u64 t; cvta.to.shared.u64 t, %1; cvt.u32.u64 %0, t; }"
        : "=r"(r) : "l"(p));
    return r;
}
__device__ __forceinline__ void cp16(uint32_t saddr, const void* gptr) {
    uint64_t g = (uint64_t)__cvta_generic_to_global(gptr);
    asm volatile("cp.async.cg.shared.global [%0], [%1], 16;"
                 :: "r"(saddr), "l"(g) : "memory");
}
__device__ __forceinline__ void cp_commit() {
    asm volatile("cp.async.commit_group;" ::: "memory");
}
template <int N>
__device__ __forceinline__ void cp_wait() {
    asm volatile("cp.async.wait_group %0;" :: "n"(N) : "memory");
}
__device__ __forceinline__ void ldsm4(uint32_t* r, uint32_t addr) {
    asm volatile("ldmatrix.sync.aligned.m8n8.x4.shared.b16 {%0,%1,%2,%3}, [%4];"
                 : "=r"(r[0]), "=r"(r[1]), "=r"(r[2]), "=r"(r[3]) : "r"(addr));
}
__device__ __forceinline__ void mma16816(float* d, const uint32_t* a, const uint32_t* b) {
    asm volatile(
        "mma.sync.aligned.m16n8k16.row.col.f32.f16.f16.f32 "
        "{%0,%1,%2,%3}, {%4,%5,%6,%7}, {%8,%9}, {%0,%1,%2,%3};"
        : "+f"(d[0]), "+f"(d[1]), "+f"(d[2]), "+f"(d[3])
        : "r"(a[0]), "r"(a[1]), "r"(a[2]), "r"(a[3]), "r"(b[0]), "r"(b[1]));
}
__device__ __forceinline__ uint32_t swz(uint32_t off) {
    return off ^ ((off >> 3) & 0x70);
}

// ---------------------------------------------------------------------------
// Operand prep
// ---------------------------------------------------------------------------
__global__ __launch_bounds__(256)
void convert_a_kernel(const float* __restrict__ A) {
    size_t i = ((size_t)blockIdx.x * 256 + threadIdx.x) * 8;
    float4 v0 = *reinterpret_cast<const float4*>(A + i);
    float4 v1 = *reinterpret_cast<const float4*>(A + i + 4);
    __half2 h0 = __floats2half2_rn(v0.x, v0.y);
    __half2 h1 = __floats2half2_rn(v0.z, v0.w);
    __half2 h2 = __floats2half2_rn(v1.x, v1.y);
    __half2 h3 = __floats2half2_rn(v1.z, v1.w);
    uint4 pk;
    pk.x = *reinterpret_cast<uint32_t*>(&h0);
    pk.y = *reinterpret_cast<uint32_t*>(&h1);
    pk.z = *reinterpret_cast<uint32_t*>(&h2);
    pk.w = *reinterpret_cast<uint32_t*>(&h3);
    *reinterpret_cast<uint4*>(g_Ah + i) = pk;
}

__global__ __launch_bounds__(256)
void convert_b_kernel(const float* __restrict__ W) {
    __shared__ float t[32][33];
    int n0 = blockIdx.x * 32;
    int k0 = blockIdx.y * 32;
    int tx = threadIdx.x & 31;
    int ty = threadIdx.x >> 5;
#pragma unroll
    for (int i = 0; i < 4; i++)
        t[ty + i * 8][tx] = W[(size_t)(k0 + ty + i * 8) * N_COLS + n0 + tx];
    __syncthreads();
#pragma unroll
    for (int i = 0; i < 4; i++) {
        int n = ty + i * 8;
        g_Bh[(size_t)(n0 + n) * K_DIM + k0 + tx] = __float2half_rn(t[tx][n]);
    }
}

// ---------------------------------------------------------------------------
// GEMM: BM=128, BN=128, BK=64, 256 threads = 8 warps (2M x 4N),
// warp tile 64x32. 3-stage cp.async pipeline, 2 CTAs per SM.
// ldsm address: base = swz(row*128 + kIn2); per-ks addr = (sbase+base) ^ ks*32.
// Valid: kIn2 (bit4) and ks*32 (bits5-6) are disjoint; swz mask hits bits 4-6;
// sbase is 128-aligned so XOR stays within the low-7-bit field.
// Epilogue: gates + per-segment scan summaries (fused phaseA, SEG_LEN=8).
// ---------------------------------------------------------------------------
#define BK 64
#define OFF_A 0
#define OFF_B 16384
#define STAGE_BYTES 32768
#define NSTAGE 3
#define SMEM_TOTAL (NSTAGE * STAGE_BYTES)   // 98304
#define NCHUNK (K_DIM / BK)                 // 16

__device__ __forceinline__ void load_stage(uint32_t sbase, int tid,
                                           int rowBase, int colBase, int k0) {
    const char* ah = reinterpret_cast<const char*>(g_Ah);
    const char* bh = reinterpret_cast<const char*>(g_Bh);
#pragma unroll
    for (int i = 0; i < 4; i++) {               // A: 128 rows x 8 x 16B
        int idx = i * 256 + tid;
        int row = idx >> 3, c = idx & 7;
        uint32_t so = swz((uint32_t)(row * 128 + c * 16));
        size_t go = ((size_t)(rowBase + row) * K_DIM + k0) * 2 + c * 16;
        cp16(sbase + OFF_A + so, ah + go);
    }
#pragma unroll
    for (int i = 0; i < 4; i++) {               // B: 128 rows x 8 x 16B
        int idx = i * 256 + tid;
        int row = idx >> 3, c = idx & 7;
        uint32_t so = swz((uint32_t)(row * 128 + c * 16));
        size_t go = ((size_t)(colBase + row) * K_DIM + k0) * 2 + c * 16;
        cp16(sbase + OFF_B + so, bh + go);
    }
    cp_commit();
}

__global__ __launch_bounds__(256, 2)
void gemm_mma_kernel(const float* __restrict__ bias,
                     float* __restrict__ u0_out,
                     float* __restrict__ f_out) {
    extern __shared__ __align__(128) char smem[];
    const uint32_t sb = s2u(smem);
    const int tid = threadIdx.x;
    const int lid = tid & 31;
    const int wid = tid >> 5;            // 0..7
    const int warpM = wid & 1;           // 2 x 64-row slices
    const int warpN = wid >> 1;          // 4 x 32-col slices
    const int colBase = blockIdx.x * 128;
    const int rowBase = blockIdx.y * 128;

    float acc[4][4][4];
#pragma unroll
    for (int mi = 0; mi < 4; mi++)
#pragma unroll
        for (int ni = 0; ni < 4; ni++)
#pragma unroll
            for (int e = 0; e < 4; e++)
                acc[mi][ni][e] = 0.0f;

    // prologue: fill 3 stages (chunks 0..2)
#pragma unroll
    for (int s = 0; s < NSTAGE; s++)
        load_stage(sb + s * STAGE_BYTES, tid, rowBase, colBase, s * BK);

    // Precomputed ldsm bases (include kIn2 inside the swizzle).
    const int aRowIn = warpM * 64 + (lid & 15);
    const int aKIn2  = ((lid >> 4) * 8) * 2;          // 0 or 16 (bit 4)
    const int bRowIn = warpN * 32 + (lid & 7) + ((lid >> 4) & 1) * 8;
    const int bKIn2  = (((lid >> 3) & 1) * 8) * 2;    // 0 or 16 (bit 4)
    uint32_t aBase[4], bBase[2];
#pragma unroll
    for (int mi = 0; mi < 4; mi++)
        aBase[mi] = swz((uint32_t)((aRowIn + mi * 16) * 128 + aKIn2)) + OFF_A;
#pragma unroll
    for (int nt = 0; nt < 2; nt++)
        bBase[nt] = swz((uint32_t)((bRowIn + nt * 16) * 128 + bKIn2)) + OFF_B;

    for (int c = 0; c < NCHUNK; c++) {
        if (c == 0)       cp_wait<2>();
        else if (c < 15)  cp_wait<1>();
        else              cp_wait<0>();
        __syncthreads();   // data visible + buffer (c-1)%3 drained by all warps

        // issue chunk c+2 into buffer (c+2)%3 == (c-1)%3 (free after barrier)
        if (c >= 1 && c + 2 < NCHUNK)
            load_stage(sb + ((c + 2) % 3) * STAGE_BYTES, tid,
                       rowBase, colBase, (c + 2) * BK);

        const uint32_t sbase = sb + (c % 3) * STAGE_BYTES;
        uint32_t aP[4], bP[2];
#pragma unroll
        for (int mi = 0; mi < 4; mi++) aP[mi] = sbase + aBase[mi];
#pragma unroll
        for (int nt = 0; nt < 2; nt++) bP[nt] = sbase + bBase[nt];

#pragma unroll
        for (int ks = 0; ks < 4; ks++) {
            const uint32_t kx = (uint32_t)(ks * 32);   // bits 5-6, XOR into field
            uint32_t ah[4][4];
#pragma unroll
            for (int mi = 0; mi < 4; mi++)
                ldsm4(ah[mi], aP[mi] ^ kx);
            uint32_t bh[4][2];
#pragma unroll
            for (int nt = 0; nt < 2; nt++) {
                uint32_t r[4];
                ldsm4(r, bP[nt] ^ kx);
                bh[nt * 2][0] = r[0]; bh[nt * 2][1] = r[1];
                bh[nt * 2 + 1][0] = r[2]; bh[nt * 2 + 1][1] = r[3];
            }
#pragma unroll
            for (int mi = 0; mi < 4; mi++)
#pragma unroll
                for (int ni = 0; ni < 4; ni++)
                    mma16816(acc[mi][ni], ah[mi], bh[ni]);
        }
    }
    __syncthreads();   // safe to reuse smem for scan partials

    // ------------- epilogue: gates + stores + fused segment summary -------------
    float2* part = reinterpret_cast<float2*>(smem);   // [wM(2)][wN(4)][ni(4)][half(2)][lane(32)]

    const int rBase = rowBase + warpM * 64 + (lid >> 2);
    const int oLane = (lid & 3);

#pragma unroll
    for (int ni = 0; ni < 4; ni++) {
        const int o = ((colBase + warpN * 32 + ni * 8) >> 1) + oLane;
        const float fb = __ldg(bias + N_OUT + o);
        float F0 = 1.0f, U0 = 0.0f, F1 = 1.0f, U1 = 0.0f;
#pragma unroll
        for (int mi = 0; mi < 4; mi++) {
            const int r0 = rBase + mi * 16;
            const int r1 = r0 + 8;
            float f0 = 1.0f / (1.0f + __expf(-(acc[mi][ni][1] + fb)));
            float u0 = acc[mi][ni][0] * (1.0f - f0);
            float f1 = 1.0f / (1.0f + __expf(-(acc[mi][ni][3] + fb)));
            float u1 = acc[mi][ni][2] * (1.0f - f1);
            u0_out[(size_t)r0 * N_OUT + o] = u0;
            f_out [(size_t)r0 * N_OUT + o] = f0;
            u0_out[(size_t)r1 * N_OUT + o] = u1;
            f_out [(size_t)r1 * N_OUT + o] = f1;
            U0 = fmaf(U0, f0, u0); F0 *= f0;
            U1 = fmaf(U1, f1, u1); F1 *= f1;
        }
        int base = ((warpM * 4 + warpN) * 4 + ni) * 64;
        part[base + lid]      = make_float2(F0, U0);
        part[base + 32 + lid] = make_float2(F1, U1);
    }
    __syncthreads();

    // combine partials across warpM (l-order) and write g_F/g_U
    const int seg = blockIdx.y;
#pragma unroll
    for (int it = 0; it < 4; it++) {
        int item = tid + it * 256;              // [wN(2b)|ni(2b)|half(1b)|lane(5b)]
        int iwN   = item >> 8;
        int ini   = (item >> 6) & 3;
        int ihalf = (item >> 5) & 1;
        int ilane = item & 31;
        float F = 1.0f, U = 0.0f;
#pragma unroll
        for (int w = 0; w < 2; w++) {
            float2 p = part[(((w * 4 + iwN) * 4 + ini) * 2 + ihalf) * 32 + ilane];
            U = fmaf(U, p.x, p.y);
            F *= p.x;
        }
        int b = (ilane >> 2) + ihalf * 8;
        int j = b * N_OUT + blockIdx.x * 64 + iwN * 16 + ini * 4 + (ilane & 3);
        g_F[seg][j] = F;
        g_U[seg][j] = U;
    }
}

// ---------------------------------------------------------------------------
// Phase B: warp-parallel affine scan over 256 segments.
// One warp per chain (lane owns 8 segments); 8 chains per block.
// Cin written in place over sF (own-warp row only — no cross-warp hazard).
// ---------------------------------------------------------------------------
__global__ __launch_bounds__(256)
void scan_phaseB(const float* __restrict__ c_init,
                 float* __restrict__ c_final) {
    __shared__ float sF[8][SEGS];
    __shared__ float sU[8][SEGS];

    const int tid = threadIdx.x;
    const int jBase = blockIdx.x * 8;

#pragma unroll
    for (int it = 0; it < 8; it++) {
        int idx = it * 256 + tid;
        int s = idx >> 3, jj = idx & 7;
        sF[jj][s] = g_F[s][jBase + jj];
        sU[jj][s] = g_U[s][jBase + jj];
    }
    __syncthreads();

    const int w = tid >> 5;
    const int lane = tid & 31;
    const int j = jBase + w;

    float Pf[8], Pu[8];
#pragma unroll
    for (int k = 0; k < 8; k++) {
        float Fk = sF[w][lane * 8 + k];
        float Uk = sU[w][lane * 8 + k];
        if (k == 0) { Pf[0] = Fk; Pu[0] = Uk; }
        else        { Pf[k] = Pf[k - 1] * Fk; Pu[k] = fmaf(Pu[k - 1], Fk, Uk); }
    }

    float tf = Pf[7], tu = Pu[7];
#pragma unroll
    for (int d = 1; d < 32; d <<= 1) {
        float of = __shfl_up_sync(0xffffffffu, tf, d);
        float ou = __shfl_up_sync(0xffffffffu, tu, d);
        if (lane >= d) {
            tu = fmaf(ou, tf, tu);
            tf = of * tf;
        }
    }
    float ef = __shfl_up_sync(0xffffffffu, tf, 1);
    float eu = __shfl_up_sync(0xffffffffu, tu, 1);
    if (lane == 0) { ef = 1.0f; eu = 0.0f; }

    const float c0 = c_init[j];
    sF[w][lane * 8] = fmaf(c0, ef, eu);
#pragma unroll
    for (int k = 1; k < 8; k++)
        sF[w][lane * 8 + k] = fmaf(c0, ef * Pf[k - 1], fmaf(eu, Pf[k - 1], Pu[k - 1]));

    if (lane == 31)
        c_final[j] = fmaf(c0, tf, tu);

    __syncthreads();
#pragma unroll
    for (int it = 0; it < 8; it++) {
        int idx = it * 256 + tid;
        int s = idx >> 3, jj = idx & 7;
        g_Cin[s][jBase + jj] = sF[jj][s];
    }
}

// ---------------------------------------------------------------------------
// Phase C: replay. 256 segments x 8 steps.
// ---------------------------------------------------------------------------
__global__ __launch_bounds__(256)
void scan_phaseC(float* __restrict__ cs,
                 const float* __restrict__ f) {
    const int j = blockIdx.x * 256 + threadIdx.x;
    const int s = blockIdx.y;
    size_t idx = (size_t)s * SEG_LEN * NCH + j;
    float c = g_Cin[s][j];
#pragma unroll
    for (int t = 0; t < SEG_LEN; t++) {
        float ft = f[idx];
        float ut = cs[idx];
        c = fmaf(c, ft, ut);
        cs[idx] = c;
        idx += NCH;
    }
}

// ---------------------------------------------------------------------------
extern "C" void kernel_launch(void* const* d_in, const int* in_sizes, int n_in,
                              void* d_out, int out_size)
{
    const float* input  = (const float*)d_in[0];
    const float* c_init = (const float*)d_in[1];
    const float* weight = (const float*)d_in[2];
    const float* bias   = (const float*)d_in[3];

    float* out    = (float*)d_out;
    float* cs     = out + CS_OFF;
    float* cfin   = out + CFINAL_OFF;
    float* forget = out + FORGET_OFF;

    cudaFuncSetAttribute(gemm_mma_kernel,
                         cudaFuncAttributeMaxDynamicSharedMemorySize, SMEM_TOTAL);

    convert_a_kernel<<<(M_ROWS * K_DIM) / (256 * 8), 256>>>(input);
    convert_b_kernel<<<dim3(N_COLS / 32, K_DIM / 32), 256>>>(weight);

    dim3 grid(N_COLS / 128, M_ROWS / 128);   // (16, 256) — blockIdx.y = segment
    gemm_mma_kernel<<<grid, 256, SMEM_TOTAL>>>(bias, cs, forget);

    scan_phaseB<<<NCH / 8, 256>>>(c_init, cfin);   // 2048 blocks, 8 chains each
    dim3 cgrid(NCH / 256, SEGS);
    scan_phaseC<<<cgrid, 256>>>(cs, forget);
}